// round 1
// baseline (speedup 1.0000x reference)
#include <cuda_runtime.h>
#include <math.h>

#define N_NODES 50000
#define N_EDGES 800000
#define DD 32
#define HH 64
#define L_LAYERS 4

typedef unsigned long long ull;

// ---------------- scratch (no cudaMalloc allowed) ----------------
__device__ float g_h[(size_t)N_NODES * DD];                     // node embeds (updated in place per layer)
__device__ float g_e[L_LAYERS + 1][(size_t)N_EDGES * DD];       // e0 (encoder) .. e4
__device__ float g_agg[(size_t)N_NODES * DD];                   // per-layer message aggregate

// ---------------- packed fp32x2 helpers ----------------
__device__ __forceinline__ ull pack2(float a, float b) {
    ull r; asm("mov.b64 %0,{%1,%2};" : "=l"(r) : "f"(a), "f"(b)); return r;
}
__device__ __forceinline__ float2 unpack2(ull v) {
    float2 r; asm("mov.b64 {%0,%1},%2;" : "=f"(r.x), "=f"(r.y) : "l"(v)); return r;
}
__device__ __forceinline__ void fma2(ull& d, ull a, ull b) {
    asm("fma.rn.f32x2 %0,%1,%2,%0;" : "+l"(d) : "l"(a), "l"(b));
}

// accumulate: acc[j] += a * Wrow[2j, 2j+1]   (OUTP pairs wide)
template <int OUTP>
__device__ __forceinline__ void consume1(float a, const float* Wrow, ull* acc) {
    ull a2 = pack2(a, a);
    const ull* w = reinterpret_cast<const ull*>(Wrow);
#pragma unroll
    for (int j = 0; j < OUTP; j++) fma2(acc[j], a2, w[j]);
}

template <int OUTP>
__device__ __forceinline__ void consume4(float4 v, const float* W, int k0, ull* acc) {
    consume1<OUTP>(v.x, W + (size_t)(k0 + 0) * (2 * OUTP), acc);
    consume1<OUTP>(v.y, W + (size_t)(k0 + 1) * (2 * OUTP), acc);
    consume1<OUTP>(v.z, W + (size_t)(k0 + 2) * (2 * OUTP), acc);
    consume1<OUTP>(v.w, W + (size_t)(k0 + 3) * (2 * OUTP), acc);
}

template <int OUTP>
__device__ __forceinline__ void init_acc(ull* acc, const float* b) {
#pragma unroll
    for (int j = 0; j < OUTP; j++) acc[j] = pack2(b[2 * j], b[2 * j + 1]);
}
template <int OUTP>
__device__ __forceinline__ void init_zero(ull* acc) {
#pragma unroll
    for (int j = 0; j < OUTP; j++) acc[j] = 0ull;
}

// relu(acc) -> per-thread smem scratch (stride 128 ull between pairs)
template <int OUTP>
__device__ __forceinline__ void relu_store(const ull* acc, ull* s) {
#pragma unroll
    for (int j = 0; j < OUTP; j++) {
        float2 v = unpack2(acc[j]);
        v.x = fmaxf(v.x, 0.f); v.y = fmaxf(v.y, 0.f);
        s[j * 128] = pack2(v.x, v.y);
    }
}

// acc += scratch_row @ W    (INP input pairs -> OUTP output pairs)
template <int INP, int OUTP>
__device__ __forceinline__ void mlp_scratch(const ull* s, const float* W, ull* acc) {
#pragma unroll 1
    for (int p = 0; p < INP; p++) {
        float2 av = unpack2(s[p * 128]);
        consume1<OUTP>(av.x, W + (size_t)(2 * p) * (2 * OUTP), acc);
        consume1<OUTP>(av.y, W + (size_t)(2 * p + 1) * (2 * OUTP), acc);
    }
}

__device__ __forceinline__ void coop_load(float* dst, const float* src, int n, int t) {
    for (int i = t; i < n; i += 128) dst[i] = src[i];
}

// ---------------- encoders ----------------
// h = relu( relu(x@W1) @ W2 )   x: [N,14], W1: 14x64, W2: 64x32
__global__ __launch_bounds__(128) void node_enc_kernel(const float* __restrict__ x,
                                                       const float* __restrict__ W1,
                                                       const float* __restrict__ W2) {
    extern __shared__ float sm[];
    float* sW1 = sm;                 // 14*64 = 896
    float* sW2 = sm + 896;           // 64*32 = 2048
    ull* scr = (ull*)(sm + 2944);    // 128*32 ull
    int t = threadIdx.x;
    coop_load(sW1, W1, 896, t);
    coop_load(sW2, W2, 2048, t);
    __syncthreads();
    int n = blockIdx.x * 128 + t;
    if (n >= N_NODES) return;
    const float* xr = x + (size_t)n * 14;
    ull acc[32]; init_zero<32>(acc);
#pragma unroll 1
    for (int k = 0; k < 14; k++) consume1<32>(xr[k], sW1 + k * 64, acc);
    relu_store<32>(acc, scr + t);
    ull acc2[16]; init_zero<16>(acc2);
    mlp_scratch<32, 16>(scr + t, sW2, acc2);
    float4* ho = (float4*)(g_h + (size_t)n * DD);
#pragma unroll
    for (int q = 0; q < 8; q++) {
        float2 v0 = unpack2(acc2[2 * q]);
        float2 v1 = unpack2(acc2[2 * q + 1]);
        float4 o;
        o.x = fmaxf(v0.x, 0.f); o.y = fmaxf(v0.y, 0.f);
        o.z = fmaxf(v1.x, 0.f); o.w = fmaxf(v1.y, 0.f);
        ho[q] = o;
    }
}

// e0 = relu( relu(ea@W1) @ W2 )   ea: [E,4]
__global__ __launch_bounds__(128) void edge_enc_kernel(const float* __restrict__ ea,
                                                       const float* __restrict__ W1,
                                                       const float* __restrict__ W2) {
    extern __shared__ float sm[];
    float* sW1 = sm;                 // 4*64 = 256
    float* sW2 = sm + 256;           // 2048
    ull* scr = (ull*)(sm + 2304);
    int t = threadIdx.x;
    coop_load(sW1, W1, 256, t);
    coop_load(sW2, W2, 2048, t);
    __syncthreads();
    int e = blockIdx.x * 128 + t;
    if (e >= N_EDGES) return;
    float4 av = ((const float4*)ea)[e];
    ull acc[32]; init_zero<32>(acc);
    consume4<32>(av, sW1, 0, acc);
    relu_store<32>(acc, scr + t);
    ull acc2[16]; init_zero<16>(acc2);
    mlp_scratch<32, 16>(scr + t, sW2, acc2);
    float4* eo = (float4*)(g_e[0] + (size_t)e * DD);
#pragma unroll
    for (int q = 0; q < 8; q++) {
        float2 v0 = unpack2(acc2[2 * q]);
        float2 v1 = unpack2(acc2[2 * q + 1]);
        float4 o;
        o.x = fmaxf(v0.x, 0.f); o.y = fmaxf(v0.y, 0.f);
        o.z = fmaxf(v1.x, 0.f); o.w = fmaxf(v1.y, 0.f);
        eo[q] = o;
    }
}

// ---------------- per-layer relational kernel ----------------
// m_in = [h[dst], h[src], e]  -> MLP3 -> e_new ; agg[dst]+=e_new ; e_out = 0.5e+0.5e_new
__global__ __launch_bounds__(128) void rel_kernel(const int* __restrict__ ei, int layer,
                                                  const float* __restrict__ W1, const float* __restrict__ b1,
                                                  const float* __restrict__ W2, const float* __restrict__ b2,
                                                  const float* __restrict__ W3, const float* __restrict__ b3) {
    extern __shared__ float sm[];
    float* sW1 = sm;                   // 96*64 = 6144
    float* sW2 = sm + 6144;            // 64*64 = 4096
    float* sW3 = sm + 10240;           // 64*32 = 2048
    float* sb1 = sm + 12288;           // 64
    float* sb2 = sm + 12352;           // 64
    float* sb3 = sm + 12416;           // 32
    ull* scr = (ull*)(sm + 12448);     // 128*32 ull
    int t = threadIdx.x;
    coop_load(sW1, W1, 6144, t);
    coop_load(sW2, W2, 4096, t);
    coop_load(sW3, W3, 2048, t);
    coop_load(sb1, b1, 64, t);
    coop_load(sb2, b2, 64, t);
    coop_load(sb3, b3, 32, t);
    __syncthreads();
    int eid = blockIdx.x * 128 + t;
    if (eid >= N_EDGES) return;
    int s = ei[eid];
    int d = ei[N_EDGES + eid];
    const float* e_in = g_e[layer];
    float* e_out = g_e[layer + 1];

    const float4* ep = (const float4*)(e_in + (size_t)eid * DD);
    float4 er[8];
#pragma unroll
    for (int q = 0; q < 8; q++) er[q] = ep[q];

    ull acc[32]; init_acc<32>(acc, sb1);
    const float4* hd = (const float4*)(g_h + (size_t)d * DD);
#pragma unroll 1
    for (int q = 0; q < 8; q++) { float4 v = hd[q]; consume4<32>(v, sW1, q * 4, acc); }
    const float4* hs = (const float4*)(g_h + (size_t)s * DD);
#pragma unroll 1
    for (int q = 0; q < 8; q++) { float4 v = hs[q]; consume4<32>(v, sW1, 32 + q * 4, acc); }
#pragma unroll 1
    for (int q = 0; q < 8; q++) { consume4<32>(er[q], sW1, 64 + q * 4, acc); }

    relu_store<32>(acc, scr + t);
    ull acc2[32]; init_acc<32>(acc2, sb2);
    mlp_scratch<32, 32>(scr + t, sW2, acc2);
    relu_store<32>(acc2, scr + t);
    ull acc3[16]; init_acc<16>(acc3, sb3);
    mlp_scratch<32, 16>(scr + t, sW3, acc3);

    float* aggrow = g_agg + (size_t)d * DD;
    float4* eo = (float4*)(e_out + (size_t)eid * DD);
#pragma unroll
    for (int q = 0; q < 8; q++) {
        float2 v0 = unpack2(acc3[2 * q]);
        float2 v1 = unpack2(acc3[2 * q + 1]);
        atomicAdd(aggrow + 4 * q + 0, v0.x);
        atomicAdd(aggrow + 4 * q + 1, v0.y);
        atomicAdd(aggrow + 4 * q + 2, v1.x);
        atomicAdd(aggrow + 4 * q + 3, v1.y);
        float4 o;
        o.x = 0.5f * er[q].x + 0.5f * v0.x;
        o.y = 0.5f * er[q].y + 0.5f * v0.y;
        o.z = 0.5f * er[q].z + 0.5f * v1.x;
        o.w = 0.5f * er[q].w + 0.5f * v1.y;
        eo[q] = o;
    }
}

// ---------------- per-layer object kernel ----------------
// h_new = MLP3([h, agg]) ; h = 0.5h + 0.5h_new  (in place)
__global__ __launch_bounds__(128) void obj_kernel(const float* __restrict__ W1, const float* __restrict__ b1,
                                                  const float* __restrict__ W2, const float* __restrict__ b2,
                                                  const float* __restrict__ W3, const float* __restrict__ b3) {
    extern __shared__ float sm[];
    float* sW1 = sm;                 // 64*64 = 4096
    float* sW2 = sm + 4096;          // 4096
    float* sW3 = sm + 8192;          // 2048
    float* sb1 = sm + 10240;
    float* sb2 = sm + 10304;
    float* sb3 = sm + 10368;
    ull* scr = (ull*)(sm + 10400);
    int t = threadIdx.x;
    coop_load(sW1, W1, 4096, t);
    coop_load(sW2, W2, 4096, t);
    coop_load(sW3, W3, 2048, t);
    coop_load(sb1, b1, 64, t);
    coop_load(sb2, b2, 64, t);
    coop_load(sb3, b3, 32, t);
    __syncthreads();
    int n = blockIdx.x * 128 + t;
    if (n >= N_NODES) return;
    const float4* hp = (const float4*)(g_h + (size_t)n * DD);
    float4 hr[8];
#pragma unroll
    for (int q = 0; q < 8; q++) hr[q] = hp[q];
    ull acc[32]; init_acc<32>(acc, sb1);
#pragma unroll 1
    for (int q = 0; q < 8; q++) { consume4<32>(hr[q], sW1, q * 4, acc); }
    const float4* ap = (const float4*)(g_agg + (size_t)n * DD);
#pragma unroll 1
    for (int q = 0; q < 8; q++) { float4 v = ap[q]; consume4<32>(v, sW1, 32 + q * 4, acc); }
    relu_store<32>(acc, scr + t);
    ull acc2[32]; init_acc<32>(acc2, sb2);
    mlp_scratch<32, 32>(scr + t, sW2, acc2);
    relu_store<32>(acc2, scr + t);
    ull acc3[16]; init_acc<16>(acc3, sb3);
    mlp_scratch<32, 16>(scr + t, sW3, acc3);
    float4* ho = (float4*)(g_h + (size_t)n * DD);
#pragma unroll
    for (int q = 0; q < 8; q++) {
        float2 v0 = unpack2(acc3[2 * q]);
        float2 v1 = unpack2(acc3[2 * q + 1]);
        float4 o;
        o.x = 0.5f * hr[q].x + 0.5f * v0.x;
        o.y = 0.5f * hr[q].y + 0.5f * v0.y;
        o.z = 0.5f * hr[q].z + 0.5f * v1.x;
        o.w = 0.5f * hr[q].w + 0.5f * v1.y;
        ho[q] = o;
    }
}

// ---------------- final edge scorer ----------------
// w_in = [h[src], h[dst], e1, e2, e3, e4] (192) -> 64 -> 64 -> 1 -> sigmoid-ish
__global__ __launch_bounds__(128) void final_kernel(const int* __restrict__ ei,
                                                    const float* __restrict__ W1, const float* __restrict__ b1,
                                                    const float* __restrict__ W2, const float* __restrict__ b2,
                                                    const float* __restrict__ W3, const float* __restrict__ b3,
                                                    float* __restrict__ out) {
    extern __shared__ float sm[];
    float* sW1 = sm;                  // 192*64 = 12288
    float* sW2 = sm + 12288;          // 4096
    float* sW3 = sm + 16384;          // 64
    float* sb1 = sm + 16448;          // 64
    float* sb2 = sm + 16512;          // 64
    float* sb3 = sm + 16576;          // 1 (+1 pad)
    ull* scr = (ull*)(sm + 16578);
    int t = threadIdx.x;
    coop_load(sW1, W1, 12288, t);
    coop_load(sW2, W2, 4096, t);
    coop_load(sW3, W3, 64, t);
    coop_load(sb1, b1, 64, t);
    coop_load(sb2, b2, 64, t);
    coop_load(sb3, b3, 1, t);
    __syncthreads();
    int eid = blockIdx.x * 128 + t;
    if (eid >= N_EDGES) return;
    int s = ei[eid];
    int d = ei[N_EDGES + eid];

    ull acc[32]; init_acc<32>(acc, sb1);
    const float4* hs = (const float4*)(g_h + (size_t)s * DD);
#pragma unroll 1
    for (int q = 0; q < 8; q++) { float4 v = hs[q]; consume4<32>(v, sW1, q * 4, acc); }
    const float4* hd = (const float4*)(g_h + (size_t)d * DD);
#pragma unroll 1
    for (int q = 0; q < 8; q++) { float4 v = hd[q]; consume4<32>(v, sW1, 32 + q * 4, acc); }
#pragma unroll 1
    for (int lay = 1; lay <= 4; lay++) {
        const float4* epp = (const float4*)(g_e[lay] + (size_t)eid * DD);
        int base = 64 + 32 * (lay - 1);
#pragma unroll 1
        for (int q = 0; q < 8; q++) { float4 v = epp[q]; consume4<32>(v, sW1, base + q * 4, acc); }
    }
    relu_store<32>(acc, scr + t);
    ull acc2[32]; init_acc<32>(acc2, sb2);
    mlp_scratch<32, 32>(scr + t, sW2, acc2);
    relu_store<32>(acc2, scr + t);
    float logit = sb3[0];
#pragma unroll 1
    for (int p = 0; p < 32; p++) {
        float2 av = unpack2((scr + t)[p * 128]);
        logit += av.x * sW3[2 * p] + av.y * sW3[2 * p + 1];
    }
    float sig = 1.f / (1.f + expf(-logit));
    out[eid] = 1e-3f + (1.f - 2e-3f) * sig;
}

// ---------------- small utility kernels ----------------
__global__ void zero_agg_kernel() {
    int i = blockIdx.x * 256 + threadIdx.x;
    if (i < N_NODES * DD) g_agg[i] = 0.f;
}

__global__ void writeback_kernel(float* __restrict__ out) {
    size_t i = (size_t)blockIdx.x * 256 + threadIdx.x;
    if (i < (size_t)N_NODES * DD) out[(size_t)N_EDGES + i] = g_h[i];
    if (i < (size_t)N_EDGES * DD) out[(size_t)N_EDGES + (size_t)N_NODES * DD + i] = g_e[4][i];
}

// ---------------- launch ----------------
extern "C" void kernel_launch(void* const* d_in, const int* in_sizes, int n_in,
                              void* d_out, int out_size) {
    const float* x      = (const float*)d_in[0];
    const int*   ei     = (const int*)d_in[1];
    const float* ea     = (const float*)d_in[2];
    const float* enW1   = (const float*)d_in[3];
    const float* enW2   = (const float*)d_in[4];
    const float* eeW1   = (const float*)d_in[5];
    const float* eeW2   = (const float*)d_in[6];
    const float* rW1    = (const float*)d_in[7];
    const float* rb1    = (const float*)d_in[8];
    const float* rW2    = (const float*)d_in[9];
    const float* rb2    = (const float*)d_in[10];
    const float* rW3    = (const float*)d_in[11];
    const float* rb3    = (const float*)d_in[12];
    const float* oW1    = (const float*)d_in[13];
    const float* ob1    = (const float*)d_in[14];
    const float* oW2    = (const float*)d_in[15];
    const float* ob2    = (const float*)d_in[16];
    const float* oW3    = (const float*)d_in[17];
    const float* ob3    = (const float*)d_in[18];
    const float* wW1    = (const float*)d_in[19];
    const float* wb1    = (const float*)d_in[20];
    const float* wW2    = (const float*)d_in[21];
    const float* wb2    = (const float*)d_in[22];
    const float* wW3    = (const float*)d_in[23];
    const float* wb3    = (const float*)d_in[24];
    float* out = (float*)d_out;

    const int NODE_SMEM = (2944) * 4 + 128 * 32 * 8;   // 44544
    const int EDGE_SMEM = (2304) * 4 + 128 * 32 * 8;   // 41984
    const int REL_SMEM  = (12448) * 4 + 128 * 32 * 8;  // 82560
    const int OBJ_SMEM  = (10400) * 4 + 128 * 32 * 8;  // 74368
    const int FIN_SMEM  = (16578) * 4 + 128 * 32 * 8;  // 99080

    cudaFuncSetAttribute(node_enc_kernel, cudaFuncAttributeMaxDynamicSharedMemorySize, NODE_SMEM);
    cudaFuncSetAttribute(edge_enc_kernel, cudaFuncAttributeMaxDynamicSharedMemorySize, EDGE_SMEM);
    cudaFuncSetAttribute(rel_kernel, cudaFuncAttributeMaxDynamicSharedMemorySize, REL_SMEM);
    cudaFuncSetAttribute(obj_kernel, cudaFuncAttributeMaxDynamicSharedMemorySize, OBJ_SMEM);
    cudaFuncSetAttribute(final_kernel, cudaFuncAttributeMaxDynamicSharedMemorySize, FIN_SMEM);

    int nodeBlocks = (N_NODES + 127) / 128;   // 391
    int edgeBlocks = (N_EDGES + 127) / 128;   // 6250

    node_enc_kernel<<<nodeBlocks, 128, NODE_SMEM>>>(x, enW1, enW2);
    edge_enc_kernel<<<edgeBlocks, 128, EDGE_SMEM>>>(ea, eeW1, eeW2);

    for (int l = 0; l < L_LAYERS; l++) {
        zero_agg_kernel<<<(N_NODES * DD + 255) / 256, 256>>>();
        rel_kernel<<<edgeBlocks, 128, REL_SMEM>>>(ei, l,
            rW1 + (size_t)l * 96 * 64, rb1 + (size_t)l * 64,
            rW2 + (size_t)l * 64 * 64, rb2 + (size_t)l * 64,
            rW3 + (size_t)l * 64 * 32, rb3 + (size_t)l * 32);
        obj_kernel<<<nodeBlocks, 128, OBJ_SMEM>>>(
            oW1 + (size_t)l * 64 * 64, ob1 + (size_t)l * 64,
            oW2 + (size_t)l * 64 * 64, ob2 + (size_t)l * 64,
            oW3 + (size_t)l * 64 * 32, ob3 + (size_t)l * 32);
    }

    final_kernel<<<edgeBlocks, 128, FIN_SMEM>>>(ei, wW1, wb1, wW2, wb2, wW3, wb3, out);

    writeback_kernel<<<((size_t)N_EDGES * DD + 255) / 256, 256>>>(out);
}

// round 3
// speedup vs baseline: 1.4112x; 1.4112x over previous
#include <cuda_runtime.h>
#include <math.h>

#define N_NODES 50000
#define N_EDGES 800000
#define DD 32
#define HH 64
#define L_LAYERS 4
#define SP 136           // padded smem row stride (floats)

typedef unsigned long long ull;

// ---------------- scratch (no cudaMalloc allowed) ----------------
__device__ float g_h[(size_t)N_NODES * DD];
__device__ float g_e[L_LAYERS + 1][(size_t)N_EDGES * DD];
__device__ float g_agg[(size_t)N_NODES * DD];

// ---------------- packed fp32x2 helpers ----------------
__device__ __forceinline__ ull pack2(float a, float b) {
    ull r; asm("mov.b64 %0,{%1,%2};" : "=l"(r) : "f"(a), "f"(b)); return r;
}
__device__ __forceinline__ float2 unpack2(ull v) {
    float2 r; asm("mov.b64 {%0,%1},%2;" : "=f"(r.x), "=f"(r.y) : "l"(v)); return r;
}
__device__ __forceinline__ void fma2(ull& d, ull a, ull b) {
    asm("fma.rn.f32x2 %0,%1,%2,%0;" : "+l"(d) : "l"(a), "l"(b));
}

__device__ __forceinline__ void coop_load(float* dst, const float* src, int n, int t, int nt) {
    for (int i = t; i < n; i += nt) dst[i] = src[i];
}

// store a float4 down a column of the transposed activation tile
__device__ __forceinline__ void st4col(float* smT, int row, int e, float4 v) {
    smT[(row + 0) * SP + e] = v.x;
    smT[(row + 1) * SP + e] = v.y;
    smT[(row + 2) * SP + e] = v.z;
    smT[(row + 3) * SP + e] = v.w;
}

// 4-edge x 8-out register-tile FMA step
__device__ __forceinline__ void tile_fma8(float4 a, const ull* wp, ull acc[4][4]) {
    ull w0 = wp[0], w1 = wp[1], w2 = wp[2], w3 = wp[3];
    ull a0 = pack2(a.x, a.x), a1 = pack2(a.y, a.y), a2 = pack2(a.z, a.z), a3 = pack2(a.w, a.w);
    fma2(acc[0][0], a0, w0); fma2(acc[0][1], a0, w1); fma2(acc[0][2], a0, w2); fma2(acc[0][3], a0, w3);
    fma2(acc[1][0], a1, w0); fma2(acc[1][1], a1, w1); fma2(acc[1][2], a1, w2); fma2(acc[1][3], a1, w3);
    fma2(acc[2][0], a2, w0); fma2(acc[2][1], a2, w1); fma2(acc[2][2], a2, w2); fma2(acc[2][3], a2, w3);
    fma2(acc[3][0], a3, w0); fma2(acc[3][1], a3, w1); fma2(acc[3][2], a3, w2); fma2(acc[3][3], a3, w3);
}

__device__ __forceinline__ void init_bias8(ull acc[4][4], const float* b, int og) {
#pragma unroll
    for (int j = 0; j < 4; j++) {
        ull bj = pack2(b[og * 8 + 2 * j], b[og * 8 + 2 * j + 1]);
#pragma unroll
        for (int i = 0; i < 4; i++) acc[i][j] = bj;
    }
}

// relu(acc) -> transposed rows [og*8 .. og*8+7], cols [4eg..4eg+3]
__device__ __forceinline__ void relu_writeH(float* smT, ull acc[4][4], int og, int eg) {
#pragma unroll
    for (int j = 0; j < 4; j++) {
        int r0 = (og * 8 + 2 * j) * SP + 4 * eg;
        int r1 = r0 + SP;
#pragma unroll
        for (int i = 0; i < 4; i++) {
            float2 v = unpack2(acc[i][j]);
            smT[r0 + i] = fmaxf(v.x, 0.f);
            smT[r1 + i] = fmaxf(v.y, 0.f);
        }
    }
}

// ---------------- per-thread helpers (encoders / obj kernel) ----------------
template <int OUTP>
__device__ __forceinline__ void consume1(float a, const float* Wrow, ull* acc) {
    ull a2 = pack2(a, a);
    const ull* w = reinterpret_cast<const ull*>(Wrow);
#pragma unroll
    for (int j = 0; j < OUTP; j++) fma2(acc[j], a2, w[j]);
}
template <int OUTP>
__device__ __forceinline__ void consume4(float4 v, const float* W, int k0, ull* acc) {
    consume1<OUTP>(v.x, W + (size_t)(k0 + 0) * (2 * OUTP), acc);
    consume1<OUTP>(v.y, W + (size_t)(k0 + 1) * (2 * OUTP), acc);
    consume1<OUTP>(v.z, W + (size_t)(k0 + 2) * (2 * OUTP), acc);
    consume1<OUTP>(v.w, W + (size_t)(k0 + 3) * (2 * OUTP), acc);
}
template <int OUTP>
__device__ __forceinline__ void init_acc(ull* acc, const float* b) {
#pragma unroll
    for (int j = 0; j < OUTP; j++) acc[j] = pack2(b[2 * j], b[2 * j + 1]);
}
template <int OUTP>
__device__ __forceinline__ void init_zero(ull* acc) {
#pragma unroll
    for (int j = 0; j < OUTP; j++) acc[j] = 0ull;
}
template <int OUTP>
__device__ __forceinline__ void relu_store(const ull* acc, ull* s) {
#pragma unroll
    for (int j = 0; j < OUTP; j++) {
        float2 v = unpack2(acc[j]);
        s[j * 128] = pack2(fmaxf(v.x, 0.f), fmaxf(v.y, 0.f));
    }
}
template <int INP, int OUTP>
__device__ __forceinline__ void mlp_scratch(const ull* s, const float* W, ull* acc) {
#pragma unroll 1
    for (int p = 0; p < INP; p++) {
        float2 av = unpack2(s[p * 128]);
        consume1<OUTP>(av.x, W + (size_t)(2 * p) * (2 * OUTP), acc);
        consume1<OUTP>(av.y, W + (size_t)(2 * p + 1) * (2 * OUTP), acc);
    }
}

__global__ __launch_bounds__(128) void node_enc_kernel(const float* __restrict__ x,
                                                       const float* __restrict__ W1,
                                                       const float* __restrict__ W2) {
    extern __shared__ float sm[];
    float* sW1 = sm;                 // 896
    float* sW2 = sm + 896;           // 2048
    ull* scr = (ull*)(sm + 2944);
    int t = threadIdx.x;
    coop_load(sW1, W1, 896, t, 128);
    coop_load(sW2, W2, 2048, t, 128);
    __syncthreads();
    int n = blockIdx.x * 128 + t;
    if (n >= N_NODES) return;
    const float* xr = x + (size_t)n * 14;
    ull acc[32]; init_zero<32>(acc);
#pragma unroll 1
    for (int k = 0; k < 14; k++) consume1<32>(xr[k], sW1 + k * 64, acc);
    relu_store<32>(acc, scr + t);
    ull acc2[16]; init_zero<16>(acc2);
    mlp_scratch<32, 16>(scr + t, sW2, acc2);
    float4* ho = (float4*)(g_h + (size_t)n * DD);
#pragma unroll
    for (int q = 0; q < 8; q++) {
        float2 v0 = unpack2(acc2[2 * q]);
        float2 v1 = unpack2(acc2[2 * q + 1]);
        float4 o;
        o.x = fmaxf(v0.x, 0.f); o.y = fmaxf(v0.y, 0.f);
        o.z = fmaxf(v1.x, 0.f); o.w = fmaxf(v1.y, 0.f);
        ho[q] = o;
    }
}

__global__ __launch_bounds__(128) void edge_enc_kernel(const float* __restrict__ ea,
                                                       const float* __restrict__ W1,
                                                       const float* __restrict__ W2) {
    extern __shared__ float sm[];
    float* sW1 = sm;                 // 256
    float* sW2 = sm + 256;           // 2048
    ull* scr = (ull*)(sm + 2304);
    int t = threadIdx.x;
    coop_load(sW1, W1, 256, t, 128);
    coop_load(sW2, W2, 2048, t, 128);
    __syncthreads();
    int e = blockIdx.x * 128 + t;
    if (e >= N_EDGES) return;
    float4 av = ((const float4*)ea)[e];
    ull acc[32]; init_zero<32>(acc);
    consume4<32>(av, sW1, 0, acc);
    relu_store<32>(acc, scr + t);
    ull acc2[16]; init_zero<16>(acc2);
    mlp_scratch<32, 16>(scr + t, sW2, acc2);
    float4* eo = (float4*)(g_e[0] + (size_t)e * DD);
#pragma unroll
    for (int q = 0; q < 8; q++) {
        float2 v0 = unpack2(acc2[2 * q]);
        float2 v1 = unpack2(acc2[2 * q + 1]);
        float4 o;
        o.x = fmaxf(v0.x, 0.f); o.y = fmaxf(v0.y, 0.f);
        o.z = fmaxf(v1.x, 0.f); o.w = fmaxf(v1.y, 0.f);
        eo[q] = o;
    }
}

// ---------------- tiled relational kernel ----------------
// block = 128 edges, 256 threads. smT[96][SP] transposed activations.
__global__ __launch_bounds__(256, 2) void rel_tile_kernel(const int* __restrict__ ei, int layer,
        const float* __restrict__ W1, const float* __restrict__ b1,
        const float* __restrict__ W2, const float* __restrict__ b2,
        const float* __restrict__ W3, const float* __restrict__ b3) {
    extern __shared__ float sm[];
    float* sW1 = sm;                    // 6144
    float* sW2 = sm + 6144;             // 4096
    float* sW3 = sm + 10240;            // 2048
    float* sb1 = sm + 12288;            // 64
    float* sb2 = sm + 12352;            // 64
    float* sb3 = sm + 12416;            // 32
    float* smT = sm + 12448;            // 96*SP = 13056  (12448 % 4 == 0 -> 16B aligned)
    int*   sdst = (int*)(sm + 12448 + 96 * SP);  // 128

    int t = threadIdx.x;
    coop_load(sW1, W1, 6144, t, 256);
    coop_load(sW2, W2, 4096, t, 256);
    coop_load(sW3, W3, 2048, t, 256);
    coop_load(sb1, b1, 64, t, 256);
    coop_load(sb2, b2, 64, t, 256);
    coop_load(sb3, b3, 32, t, 256);

    const float* e_in = g_e[layer];
    float* e_out = g_e[layer + 1];
    int blk = blockIdx.x * 128;

    // ---- gather/fill transposed activations ----
    {
        int e = t & 127, part = t >> 7;
        int eid = blk + e;
        int s = ei[eid];
        int d = ei[N_EDGES + eid];
        if (part == 0) sdst[e] = d;
        const float4* hd = (const float4*)(g_h + (size_t)d * DD);
        const float4* hs = (const float4*)(g_h + (size_t)s * DD);
        const float4* ep = (const float4*)(e_in + (size_t)eid * DD);
        if (part == 0) {
#pragma unroll
            for (int q = 0; q < 8; q++) st4col(smT, 4 * q, e, hd[q]);
#pragma unroll
            for (int q = 0; q < 4; q++) st4col(smT, 32 + 4 * q, e, hs[q]);
        } else {
#pragma unroll
            for (int q = 4; q < 8; q++) st4col(smT, 32 + 4 * q, e, hs[q]);
#pragma unroll
            for (int q = 0; q < 8; q++) st4col(smT, 64 + 4 * q, e, ep[q]);
        }
    }
    __syncthreads();

    int eg = t & 31;       // edges 4eg..4eg+3
    int og = t >> 5;       // outs 8og..8og+7

    // ---- layer 1: 96 -> 64 ----
    ull acc[4][4];
    init_bias8(acc, sb1, og);
#pragma unroll 2
    for (int k = 0; k < 96; k++) {
        float4 a = *(const float4*)&smT[k * SP + 4 * eg];
        tile_fma8(a, (const ull*)&sW1[k * 64 + og * 8], acc);
    }
    __syncthreads();
    relu_writeH(smT, acc, og, eg);
    __syncthreads();

    // ---- layer 2: 64 -> 64 ----
    init_bias8(acc, sb2, og);
#pragma unroll 2
    for (int k = 0; k < 64; k++) {
        float4 a = *(const float4*)&smT[k * SP + 4 * eg];
        tile_fma8(a, (const ull*)&sW2[k * 64 + og * 8], acc);
    }
    __syncthreads();
    relu_writeH(smT, acc, og, eg);
    __syncthreads();

    // ---- layer 3: 64 -> 32 (4-edge x 4-out tile) ----
    ull acc3[4][2];
#pragma unroll
    for (int j = 0; j < 2; j++) {
        ull bj = pack2(sb3[og * 4 + 2 * j], sb3[og * 4 + 2 * j + 1]);
#pragma unroll
        for (int i = 0; i < 4; i++) acc3[i][j] = bj;
    }
#pragma unroll 2
    for (int k = 0; k < 64; k++) {
        float4 a = *(const float4*)&smT[k * SP + 4 * eg];
        const ull* wp = (const ull*)&sW3[k * 32 + og * 4];
        ull w0 = wp[0], w1 = wp[1];
        ull a0 = pack2(a.x, a.x), a1 = pack2(a.y, a.y), a2 = pack2(a.z, a.z), a3 = pack2(a.w, a.w);
        fma2(acc3[0][0], a0, w0); fma2(acc3[0][1], a0, w1);
        fma2(acc3[1][0], a1, w0); fma2(acc3[1][1], a1, w1);
        fma2(acc3[2][0], a2, w0); fma2(acc3[2][1], a2, w1);
        fma2(acc3[3][0], a3, w0); fma2(acc3[3][1], a3, w1);
    }

    // ---- epilogue: residual e_out, atomic agg ----
#pragma unroll
    for (int i = 0; i < 4; i++) {
        int e_i = 4 * eg + i;
        int eid_i = blk + e_i;
        int d_i = sdst[e_i];
#pragma unroll
        for (int jp = 0; jp < 2; jp++) {
            int c = og * 4 + 2 * jp;
            float2 v = unpack2(acc3[i][jp]);
            float ein0 = smT[(64 + c) * SP + e_i];
            float ein1 = smT[(64 + c + 1) * SP + e_i];
            float2 o;
            o.x = 0.5f * ein0 + 0.5f * v.x;
            o.y = 0.5f * ein1 + 0.5f * v.y;
            *(float2*)&e_out[(size_t)eid_i * DD + c] = o;
            atomicAdd(&g_agg[(size_t)d_i * DD + c], v.x);
            atomicAdd(&g_agg[(size_t)d_i * DD + c + 1], v.y);
        }
    }
}

// ---------------- object kernel (node update) ----------------
__global__ __launch_bounds__(128) void obj_kernel(const float* __restrict__ W1, const float* __restrict__ b1,
                                                  const float* __restrict__ W2, const float* __restrict__ b2,
                                                  const float* __restrict__ W3, const float* __restrict__ b3) {
    extern __shared__ float sm[];
    float* sW1 = sm;
    float* sW2 = sm + 4096;
    float* sW3 = sm + 8192;
    float* sb1 = sm + 10240;
    float* sb2 = sm + 10304;
    float* sb3 = sm + 10368;
    ull* scr = (ull*)(sm + 10400);
    int t = threadIdx.x;
    coop_load(sW1, W1, 4096, t, 128);
    coop_load(sW2, W2, 4096, t, 128);
    coop_load(sW3, W3, 2048, t, 128);
    coop_load(sb1, b1, 64, t, 128);
    coop_load(sb2, b2, 64, t, 128);
    coop_load(sb3, b3, 32, t, 128);
    __syncthreads();
    int n = blockIdx.x * 128 + t;
    if (n >= N_NODES) return;
    const float4* hp = (const float4*)(g_h + (size_t)n * DD);
    float4 hr[8];
#pragma unroll
    for (int q = 0; q < 8; q++) hr[q] = hp[q];
    ull acc[32]; init_acc<32>(acc, sb1);
#pragma unroll 1
    for (int q = 0; q < 8; q++) { consume4<32>(hr[q], sW1, q * 4, acc); }
    const float4* ap = (const float4*)(g_agg + (size_t)n * DD);
#pragma unroll 1
    for (int q = 0; q < 8; q++) { float4 v = ap[q]; consume4<32>(v, sW1, 32 + q * 4, acc); }
    relu_store<32>(acc, scr + t);
    ull acc2[32]; init_acc<32>(acc2, sb2);
    mlp_scratch<32, 32>(scr + t, sW2, acc2);
    relu_store<32>(acc2, scr + t);
    ull acc3[16]; init_acc<16>(acc3, sb3);
    mlp_scratch<32, 16>(scr + t, sW3, acc3);
    float4* ho = (float4*)(g_h + (size_t)n * DD);
#pragma unroll
    for (int q = 0; q < 8; q++) {
        float2 v0 = unpack2(acc3[2 * q]);
        float2 v1 = unpack2(acc3[2 * q + 1]);
        float4 o;
        o.x = 0.5f * hr[q].x + 0.5f * v0.x;
        o.y = 0.5f * hr[q].y + 0.5f * v0.y;
        o.z = 0.5f * hr[q].z + 0.5f * v1.x;
        o.w = 0.5f * hr[q].w + 0.5f * v1.y;
        ho[q] = o;
    }
}

// ---------------- tiled final edge scorer ----------------
// w_in = [h_src, h_dst, e1..e4] (192) -> 64 -> 64 -> 1, two-pass k staging
__global__ __launch_bounds__(256, 2) void final_tile_kernel(const int* __restrict__ ei,
        const float* __restrict__ W1, const float* __restrict__ b1,
        const float* __restrict__ W2, const float* __restrict__ b2,
        const float* __restrict__ W3, const float* __restrict__ b3,
        float* __restrict__ out) {
    extern __shared__ float sm[];
    float* sW1 = sm;                    // 6144 (staged half of 192x64)
    float* sW2 = sm + 6144;             // 4096
    float* sW3 = sm + 10240;            // 64
    float* sb1 = sm + 10304;            // 64
    float* sb2 = sm + 10368;            // 64
    float* sb3 = sm + 10432;            // 1 (+3 pad)
    float* smT = sm + 10436;            // 96*SP  (10436 % 4 == 0 -> 16B aligned)

    int t = threadIdx.x;
    coop_load(sW1, W1, 6144, t, 256);   // rows 0..95
    coop_load(sW2, W2, 4096, t, 256);
    coop_load(sW3, W3, 64, t, 256);
    coop_load(sb1, b1, 64, t, 256);
    coop_load(sb2, b2, 64, t, 256);
    if (t == 0) sb3[0] = b3[0];

    int blk = blockIdx.x * 128;
    int e = t & 127, part = t >> 7;
    int eid = blk + e;
    int s = ei[eid];
    int d = ei[N_EDGES + eid];

    // ---- pass A fill: h_src(0..31), h_dst(32..63), e1(64..95) ----
    {
        const float4* hs = (const float4*)(g_h + (size_t)s * DD);
        const float4* hd = (const float4*)(g_h + (size_t)d * DD);
        const float4* e1 = (const float4*)(g_e[1] + (size_t)eid * DD);
        if (part == 0) {
#pragma unroll
            for (int q = 0; q < 8; q++) st4col(smT, 4 * q, e, hs[q]);
#pragma unroll
            for (int q = 0; q < 4; q++) st4col(smT, 32 + 4 * q, e, hd[q]);
        } else {
#pragma unroll
            for (int q = 4; q < 8; q++) st4col(smT, 32 + 4 * q, e, hd[q]);
#pragma unroll
            for (int q = 0; q < 8; q++) st4col(smT, 64 + 4 * q, e, e1[q]);
        }
    }
    __syncthreads();

    int eg = t & 31, og = t >> 5;
    ull acc[4][4];
    init_bias8(acc, sb1, og);
#pragma unroll 2
    for (int k = 0; k < 96; k++) {
        float4 a = *(const float4*)&smT[k * SP + 4 * eg];
        tile_fma8(a, (const ull*)&sW1[k * 64 + og * 8], acc);
    }
    __syncthreads();

    // ---- pass B fill: e2(0..31), e3(32..63), e4(64..95) + W1 rows 96..191 ----
    {
        const float4* e2 = (const float4*)(g_e[2] + (size_t)eid * DD);
        const float4* e3 = (const float4*)(g_e[3] + (size_t)eid * DD);
        const float4* e4 = (const float4*)(g_e[4] + (size_t)eid * DD);
        if (part == 0) {
#pragma unroll
            for (int q = 0; q < 8; q++) st4col(smT, 4 * q, e, e2[q]);
#pragma unroll
            for (int q = 0; q < 4; q++) st4col(smT, 32 + 4 * q, e, e3[q]);
        } else {
#pragma unroll
            for (int q = 4; q < 8; q++) st4col(smT, 32 + 4 * q, e, e3[q]);
#pragma unroll
            for (int q = 0; q < 8; q++) st4col(smT, 64 + 4 * q, e, e4[q]);
        }
    }
    coop_load(sW1, W1 + 96 * 64, 6144, t, 256);
    __syncthreads();

#pragma unroll 2
    for (int k = 0; k < 96; k++) {
        float4 a = *(const float4*)&smT[k * SP + 4 * eg];
        tile_fma8(a, (const ull*)&sW1[k * 64 + og * 8], acc);
    }
    __syncthreads();
    relu_writeH(smT, acc, og, eg);
    __syncthreads();

    // ---- layer 2: 64 -> 64 ----
    init_bias8(acc, sb2, og);
#pragma unroll 2
    for (int k = 0; k < 64; k++) {
        float4 a = *(const float4*)&smT[k * SP + 4 * eg];
        tile_fma8(a, (const ull*)&sW2[k * 64 + og * 8], acc);
    }
    __syncthreads();
    relu_writeH(smT, acc, og, eg);
    __syncthreads();

    // ---- layer 3: dot(64) -> sigmoid ----
    if (t < 128) {
        float logit = sb3[0];
#pragma unroll 2
        for (int k = 0; k < 64; k++) logit += smT[k * SP + t] * sW3[k];
        float sig = 1.f / (1.f + expf(-logit));
        out[blk + t] = 1e-3f + (1.f - 2e-3f) * sig;
    }
}

// ---------------- utility ----------------
__global__ void zero_agg_kernel() {
    int i = blockIdx.x * 256 + threadIdx.x;
    if (i < N_NODES * DD) g_agg[i] = 0.f;
}

__global__ void writeback_kernel(float* __restrict__ out) {
    size_t i = (size_t)blockIdx.x * 256 + threadIdx.x;
    if (i < (size_t)N_NODES * DD) out[(size_t)N_EDGES + i] = g_h[i];
    if (i < (size_t)N_EDGES * DD) out[(size_t)N_EDGES + (size_t)N_NODES * DD + i] = g_e[4][i];
}

// ---------------- launch ----------------
extern "C" void kernel_launch(void* const* d_in, const int* in_sizes, int n_in,
                              void* d_out, int out_size) {
    const float* x      = (const float*)d_in[0];
    const int*   ei     = (const int*)d_in[1];
    const float* ea     = (const float*)d_in[2];
    const float* enW1   = (const float*)d_in[3];
    const float* enW2   = (const float*)d_in[4];
    const float* eeW1   = (const float*)d_in[5];
    const float* eeW2   = (const float*)d_in[6];
    const float* rW1    = (const float*)d_in[7];
    const float* rb1    = (const float*)d_in[8];
    const float* rW2    = (const float*)d_in[9];
    const float* rb2    = (const float*)d_in[10];
    const float* rW3    = (const float*)d_in[11];
    const float* rb3    = (const float*)d_in[12];
    const float* oW1    = (const float*)d_in[13];
    const float* ob1    = (const float*)d_in[14];
    const float* oW2    = (const float*)d_in[15];
    const float* ob2    = (const float*)d_in[16];
    const float* oW3    = (const float*)d_in[17];
    const float* ob3    = (const float*)d_in[18];
    const float* wW1    = (const float*)d_in[19];
    const float* wb1    = (const float*)d_in[20];
    const float* wW2    = (const float*)d_in[21];
    const float* wb2    = (const float*)d_in[22];
    const float* wW3    = (const float*)d_in[23];
    const float* wb3    = (const float*)d_in[24];
    float* out = (float*)d_out;

    const int NODE_SMEM = 2944 * 4 + 128 * 32 * 8;
    const int EDGE_SMEM = 2304 * 4 + 128 * 32 * 8;
    const int OBJ_SMEM  = 10400 * 4 + 128 * 32 * 8;
    const int REL_SMEM  = (12448 + 96 * SP + 128) * 4;       // ~102.5KB
    const int FIN_SMEM  = (10436 + 96 * SP) * 4;             // ~94KB

    cudaFuncSetAttribute(node_enc_kernel, cudaFuncAttributeMaxDynamicSharedMemorySize, NODE_SMEM);
    cudaFuncSetAttribute(edge_enc_kernel, cudaFuncAttributeMaxDynamicSharedMemorySize, EDGE_SMEM);
    cudaFuncSetAttribute(obj_kernel, cudaFuncAttributeMaxDynamicSharedMemorySize, OBJ_SMEM);
    cudaFuncSetAttribute(rel_tile_kernel, cudaFuncAttributeMaxDynamicSharedMemorySize, REL_SMEM);
    cudaFuncSetAttribute(final_tile_kernel, cudaFuncAttributeMaxDynamicSharedMemorySize, FIN_SMEM);

    int nodeBlocks = (N_NODES + 127) / 128;
    int edgeBlocks128t = (N_EDGES + 127) / 128;
    int tileBlocks = N_EDGES / 128;   // 6250 exact

    node_enc_kernel<<<nodeBlocks, 128, NODE_SMEM>>>(x, enW1, enW2);
    edge_enc_kernel<<<edgeBlocks128t, 128, EDGE_SMEM>>>(ea, eeW1, eeW2);

    for (int l = 0; l < L_LAYERS; l++) {
        zero_agg_kernel<<<(N_NODES * DD + 255) / 256, 256>>>();
        rel_tile_kernel<<<tileBlocks, 256, REL_SMEM>>>(ei, l,
            rW1 + (size_t)l * 96 * 64, rb1 + (size_t)l * 64,
            rW2 + (size_t)l * 64 * 64, rb2 + (size_t)l * 64,
            rW3 + (size_t)l * 64 * 32, rb3 + (size_t)l * 32);
        obj_kernel<<<nodeBlocks, 128, OBJ_SMEM>>>(
            oW1 + (size_t)l * 64 * 64, ob1 + (size_t)l * 64,
            oW2 + (size_t)l * 64 * 64, ob2 + (size_t)l * 64,
            oW3 + (size_t)l * 64 * 32, ob3 + (size_t)l * 32);
    }

    final_tile_kernel<<<tileBlocks, 256, FIN_SMEM>>>(ei, wW1, wb1, wW2, wb2, wW3, wb3, out);

    writeback_kernel<<<((size_t)N_EDGES * DD + 255) / 256, 256>>>(out);
}